// round 13
// baseline (speedup 1.0000x reference)
#include <cuda_runtime.h>
#include <cuda_bf16.h>
#include <cstdint>
#include <math.h>

#define Bz 512
#define Lz 200
#define Ez 256
#define Hz 128
#define G4 512          // 4*H
#define Dz 256
#define Tz 6
#define NL (Bz*Lz)      // 102400

typedef unsigned long long u64t;

// ---------------- device scratch ----------------
__device__ float g_X[NL*Dz];          // h2 (MLP2 fp32 output)
__device__ float g_xgf[NL*G4];        // forward input gates (fp32)
__device__ float g_xgb[NL*G4];        // backward input gates (fp32)
__device__ float g_logits[NL*Tz];     // emissions, TRANSPOSED layout [L][B][T]
__device__ float g_Whh4_f[Hz*G4];
__device__ float g_Whh4_b[Hz*G4];

// bf16 split-2 operand buffers (value = hi + lo)
__device__ __nv_bfloat16 g_Xh[NL*Ez],  g_Xl[NL*Ez];     // embeddings
__device__ __nv_bfloat16 g_Hh[NL*Dz],  g_Hl[NL*Dz];     // BiLSTM hidden
__device__ __nv_bfloat16 g_M1h[NL*Dz], g_M1l[NL*Dz];    // MLP1 out
__device__ __nv_bfloat16 g_WFh[G4*Ez], g_WFl[G4*Ez];    // Wih_f
__device__ __nv_bfloat16 g_WBh[G4*Ez], g_WBl[G4*Ez];    // Wih_b
__device__ __nv_bfloat16 g_W1h[Dz*Dz], g_W1l[Dz*Dz];
__device__ __nv_bfloat16 g_W2h[Dz*Dz], g_W2l[Dz*Dz];

// ================= helpers =================
__device__ __forceinline__ uint32_t smem_u32(const void* p) {
    uint32_t a;
    asm("{ .reg .u64 t; cvta.to.shared.u64 t, %1; cvt.u32.u64 %0, t; }" : "=r"(a) : "l"(p));
    return a;
}
__device__ __forceinline__ uint32_t swz(uint32_t off) {        // SW128-style XOR swizzle
    return off ^ ((off >> 3) & 0x70);
}
__device__ __forceinline__ void ldm4(uint32_t* r, uint32_t addr) {
    asm volatile("ldmatrix.sync.aligned.m8n8.x4.shared.b16 {%0,%1,%2,%3}, [%4];"
        : "=r"(r[0]), "=r"(r[1]), "=r"(r[2]), "=r"(r[3]) : "r"(addr));
}
__device__ __forceinline__ void mma16816(float* d, const uint32_t* a, const uint32_t* b) {
    asm volatile("mma.sync.aligned.m16n8k16.row.col.f32.bf16.bf16.f32 "
        "{%0,%1,%2,%3}, {%4,%5,%6,%7}, {%8,%9}, {%0,%1,%2,%3};"
        : "+f"(d[0]), "+f"(d[1]), "+f"(d[2]), "+f"(d[3])
        : "r"(a[0]), "r"(a[1]), "r"(a[2]), "r"(a[3]), "r"(b[0]), "r"(b[1]));
}
__device__ __forceinline__ void split2(float x, __nv_bfloat16& h, __nv_bfloat16& l) {
    h = __float2bfloat16(x);
    l = __float2bfloat16(x - __bfloat162float(h));
}
__device__ __forceinline__ void cp16(uint32_t dst, const void* src) {
    asm volatile("cp.async.cg.shared.global [%0], [%1], 16;" :: "r"(dst), "l"(src));
}
// packed f32x2 FMA (Blackwell). Pure (no memory side effects) -> schedulable.
__device__ __forceinline__ u64t fma2(u64t a, u64t b, u64t c) {
    u64t d;
    asm("fma.rn.f32x2 %0, %1, %2, %3;" : "=l"(d) : "l"(a), "l"(b), "l"(c));
    return d;
}
__device__ __forceinline__ u64t pack2(float x, float y) {
    u64t r; asm("mov.b64 %0, {%1, %2};" : "=l"(r) : "f"(x), "f"(y)); return r;
}
__device__ __forceinline__ float hadd2(u64t v) {
    float x, y;
    asm("mov.b64 {%0, %1}, %2;" : "=f"(x), "=f"(y) : "l"(v));
    return x + y;
}

// ---------------- gather embeddings -> bf16 split2 ----------------
__global__ void gather_conv(const int* __restrict__ sent, const float* __restrict__ emb) {
    int idx = blockIdx.x * 256 + threadIdx.x;     // float4 units over NL x 256
    if (idx >= NL * (Ez / 4)) return;
    int n = idx >> 6, e4 = idx & 63;
    int tok = sent[n];
    float4 v = ((const float4*)emb)[(size_t)tok * 64 + e4];
    size_t o = (size_t)idx * 4;
    float vv[4] = {v.x, v.y, v.z, v.w};
    __nv_bfloat16 hh[4], ll[4];
    #pragma unroll
    for (int k = 0; k < 4; k++) split2(vv[k], hh[k], ll[k]);
    __nv_bfloat162 p;
    p.x = hh[0]; p.y = hh[1]; ((__nv_bfloat162*)(g_Xh + o))[0] = p;
    p.x = hh[2]; p.y = hh[3]; ((__nv_bfloat162*)(g_Xh + o))[1] = p;
    p.x = ll[0]; p.y = ll[1]; ((__nv_bfloat162*)(g_Xl + o))[0] = p;
    p.x = ll[2]; p.y = ll[3]; ((__nv_bfloat162*)(g_Xl + o))[1] = p;
}

// ---------------- all weight conversions in ONE kernel ----------------
// WF (131072), WB (131072), W1 (65536), W2 (65536) => total 393216 elements
__global__ void conv_all(const float* __restrict__ Wih_f, const float* __restrict__ Wih_b,
                         const float* __restrict__ W1, const float* __restrict__ W2) {
    int i = blockIdx.x * 256 + threadIdx.x;
    const float* src; __nv_bfloat16 *hi, *lo; int off;
    if (i < 131072)      { src = Wih_f; hi = g_WFh; lo = g_WFl; off = i; }
    else if (i < 262144) { src = Wih_b; hi = g_WBh; lo = g_WBl; off = i - 131072; }
    else if (i < 327680) { src = W1;    hi = g_W1h; lo = g_W1l; off = i - 262144; }
    else if (i < 393216) { src = W2;    hi = g_W2h; lo = g_W2l; off = i - 327680; }
    else return;
    __nv_bfloat16 h, l;
    split2(src[off], h, l);
    hi[off] = h; lo[off] = l;
}

// ---------------- repack Whh ----------------
__global__ void prep_whh(const float* __restrict__ Whh_f, const float* __restrict__ Whh_b) {
    int idx = blockIdx.x * 256 + threadIdx.x;
    if (idx >= G4 * Hz) return;
    int g = idx / Hz, k = idx % Hz;
    int dst = (k >> 2) * (G4 * 4) + g * 4 + (k & 3);
    g_Whh4_f[dst] = Whh_f[idx];
    g_Whh4_b[dst] = Whh_b[idx];
}

// ================= HMMA split-bf16 GEMM (cp.async double-buffered) =================
#define GEMM_SMEM 65536
__global__ __launch_bounds__(256) void gemm_mma(
    const __nv_bfloat16* __restrict__ Ah, const __nv_bfloat16* __restrict__ Al,
    const __nv_bfloat16* __restrict__ Bh, const __nv_bfloat16* __restrict__ Bl,
    const float* __restrict__ bias1, const float* __restrict__ bias2,
    float* __restrict__ Cf,
    __nv_bfloat16* __restrict__ C2h, __nv_bfloat16* __restrict__ C2l,
    int Mout, int mode)
{
    extern __shared__ __align__(1024) char dynsm[];
    uint32_t smem_base = smem_u32(dynsm);

    int tid = threadIdx.x, wid = tid >> 5, lane = tid & 31;
    int row0 = blockIdx.y * 128;
    int col0 = blockIdx.x * 128;
    int wm0 = (wid & 1) * 64;
    int wn0 = (wid >> 1) * 32;

    float acc[4][4][4];
    #pragma unroll
    for (int i = 0; i < 4; i++)
        #pragma unroll
        for (int j = 0; j < 4; j++)
            #pragma unroll
            for (int k = 0; k < 4; k++) acc[i][j][k] = 0.f;

    int arow = ((lane >> 3) & 1) * 8 + (lane & 7);
    int acb  = (lane >> 4) << 4;
    int brow = ((lane >> 4) << 3) + (lane & 7);
    int bcb  = ((lane >> 3) & 1) << 4;

#define LOAD_CHUNK(kcv, bufi) do {                                                      \
        int k0_ = (kcv) * 32;                                                           \
        uint32_t sb_ = smem_base + (bufi) * 32768;                                      \
        _Pragma("unroll")                                                               \
        for (int j_ = 0; j_ < 4; j_++) {                                                \
            int idx_ = tid + j_ * 256;                                                  \
            int r_ = idx_ >> 3, s_ = idx_ & 7;                                          \
            const __nv_bfloat16* pa_ = (s_ < 4 ? Ah : Al) + (size_t)(row0 + r_) * 256 + k0_ + (s_ & 3) * 8; \
            cp16(sb_ + swz(r_ * 128 + s_ * 16), pa_);                                   \
            const __nv_bfloat16* pb_ = (s_ < 4 ? Bh : Bl) + (size_t)(col0 + r_) * 256 + k0_ + (s_ & 3) * 8; \
            cp16(sb_ + 16384 + swz(r_ * 128 + s_ * 16), pb_);                           \
        }                                                                               \
        asm volatile("cp.async.commit_group;" ::: "memory");                            \
    } while (0)

    LOAD_CHUNK(0, 0);

    for (int kc = 0; kc < 8; kc++) {
        if (kc < 7) {
            LOAD_CHUNK(kc + 1, (kc + 1) & 1);
            asm volatile("cp.async.wait_group 1;" ::: "memory");
        } else {
            asm volatile("cp.async.wait_group 0;" ::: "memory");
        }
        __syncthreads();

        uint32_t sA = smem_base + (kc & 1) * 32768;
        uint32_t sB = sA + 16384;

        #pragma unroll
        for (int ks = 0; ks < 2; ks++) {
            uint32_t aH[4][4], aL[4][4], bH[2][4], bL[2][4];
            #pragma unroll
            for (int am = 0; am < 4; am++) {
                int r = wm0 + am * 16 + arow;
                ldm4(aH[am], sA + swz((uint32_t)(r * 128 + ks * 32 + acb)));
                ldm4(aL[am], sA + swz((uint32_t)(r * 128 + 64 + ks * 32 + acb)));
            }
            #pragma unroll
            for (int np = 0; np < 2; np++) {
                int r = wn0 + np * 16 + brow;
                ldm4(bH[np], sB + swz((uint32_t)(r * 128 + ks * 32 + bcb)));
                ldm4(bL[np], sB + swz((uint32_t)(r * 128 + 64 + ks * 32 + bcb)));
            }
            #pragma unroll
            for (int am = 0; am < 4; am++) {
                #pragma unroll
                for (int bn = 0; bn < 4; bn++) {
                    const uint32_t* bh = &bH[bn >> 1][(bn & 1) * 2];
                    const uint32_t* bl = &bL[bn >> 1][(bn & 1) * 2];
                    mma16816(acc[am][bn], aH[am], bh);
                    mma16816(acc[am][bn], aH[am], bl);
                    mma16816(acc[am][bn], aL[am], bh);
                }
            }
        }
        __syncthreads();
    }
#undef LOAD_CHUNK

    int rg = row0 + wm0 + (lane >> 2);
    int cg = col0 + wn0 + (lane & 3) * 2;
    #pragma unroll
    for (int bn = 0; bn < 4; bn++) {
        int col = cg + bn * 8;
        float bb0 = bias1[col]     + (bias2 ? bias2[col]     : 0.f);
        float bb1 = bias1[col + 1] + (bias2 ? bias2[col + 1] : 0.f);
        #pragma unroll
        for (int am = 0; am < 4; am++) {
            #pragma unroll
            for (int half = 0; half < 2; half++) {
                int row = rg + am * 16 + half * 8;
                float x0 = acc[am][bn][half * 2]     + bb0;
                float x1 = acc[am][bn][half * 2 + 1] + bb1;
                if (mode) {
                    x0 = x0 >= 0.f ? x0 : 0.01f * x0;
                    x1 = x1 >= 0.f ? x1 : 0.01f * x1;
                }
                size_t base = (size_t)row * Mout + col;
                if (mode <= 1) {
                    float2 v; v.x = x0; v.y = x1;
                    *(float2*)(Cf + base) = v;
                } else {
                    __nv_bfloat16 h0, l0, h1, l1;
                    split2(x0, h0, l0);
                    split2(x1, h1, l1);
                    __nv_bfloat162 ph, pl;
                    ph.x = h0; ph.y = h1;
                    pl.x = l0; pl.y = l1;
                    *(__nv_bfloat162*)(C2h + base) = ph;
                    *(__nv_bfloat162*)(C2l + base) = pl;
                }
            }
        }
    }
}

// ---------------- BiLSTM recurrence ----------------
// 20/32 kc-chunks (160KB) of Whh staged in dynamic SMEM; remaining 12 chunks
// hoisted ONCE into registers (loop-invariant). All shared accesses are plain
// C++ loads/stores: ordered w.r.t. __syncthreads() by language semantics
// (fixes R10 corruption) yet freely schedulable (fixes R12 serialization).
// xg gate-inputs for step t+1 prefetched during step t. EXACT activations.
#define KC_SM 20
#define KC_LD (Hz/4 - KC_SM)     // 12
#define LSTM_DYN (KC_SM * 2048 * 4)
__global__ __launch_bounds__(512) void lstm_kernel() {
    extern __shared__ __align__(16) float sw[];    // [KC_SM][2048]
    __shared__ float hs[8][Hz];
    __shared__ float cs[8][Hz];
    __shared__ float gb[8][G4];

    int dir = blockIdx.y;
    int b0  = blockIdx.x * 8;
    const float* xg = dir ? g_xgb : g_xgf;
    const float* W4 = dir ? g_Whh4_b : g_Whh4_f;

    int g = threadIdx.x;
    // cooperative smem weight load
    for (int i = g * 4; i < KC_SM * 2048; i += 512 * 4)
        *(float4*)(sw + i) = *(const float4*)(W4 + i);
    for (int idx = g; idx < 8 * Hz; idx += 512) {
        ((float*)hs)[idx] = 0.f;
        ((float*)cs)[idx] = 0.f;
    }
    __syncthreads();

    // hoist the 12 non-smem weight chunks into registers (loop-invariant)
    const float* wg0 = W4 + KC_SM * 2048 + (g << 2);
    ulonglong2 wp[KC_LD];
    #pragma unroll
    for (int kc = 0; kc < KC_LD; kc++)
        wp[kc] = *(const ulonglong2*)(wg0 + kc * 2048);

    int pos0 = dir ? (Lz - 1) : 0;
    int sdir = dir ? -1 : 1;

    // preload xg for step 0
    float xcur[8];
    #pragma unroll
    for (int r = 0; r < 8; r++)
        xcur[r] = xg[((size_t)(b0 + r) * Lz + pos0) * G4 + g];

    for (int t = 0; t < Lz; t++) {
        int pos = pos0 + t * sdir;

        // prefetch next step's xg (hides DRAM latency behind the matvec)
        float xnext[8];
        if (t + 1 < Lz) {
            int pn = pos + sdir;
            #pragma unroll
            for (int r = 0; r < 8; r++)
                xnext[r] = xg[((size_t)(b0 + r) * Lz + pn) * G4 + g];
        }

        u64t acc[8];
        #pragma unroll
        for (int r = 0; r < 8; r++) acc[r] = pack2(xcur[r], 0.f);

        // smem-weight portion (plain loads)
        #pragma unroll 4
        for (int kc = 0; kc < KC_SM; kc++) {
            ulonglong2 wv = *(const ulonglong2*)(sw + kc * 2048 + (g << 2));
            #pragma unroll
            for (int r = 0; r < 8; r++) {
                ulonglong2 hv = *(const ulonglong2*)(&hs[r][kc << 2]);
                acc[r] = fma2(wv.x, hv.x, acc[r]);
                acc[r] = fma2(wv.y, hv.y, acc[r]);
            }
        }
        // register-resident weight portion
        #pragma unroll
        for (int kc = 0; kc < KC_LD; kc++) {
            #pragma unroll
            for (int r = 0; r < 8; r++) {
                ulonglong2 hv = *(const ulonglong2*)(&hs[r][(KC_SM + kc) << 2]);
                acc[r] = fma2(wp[kc].x, hv.x, acc[r]);
                acc[r] = fma2(wp[kc].y, hv.y, acc[r]);
            }
        }
        #pragma unroll
        for (int r = 0; r < 8; r++) gb[r][g] = hadd2(acc[r]);
        __syncthreads();

        #pragma unroll
        for (int rep = 0; rep < 2; rep++) {
            int idx = rep * 512 + g;
            int r = idx >> 7, j = idx & 127;
            float xi = gb[r][j];
            float xf = gb[r][j + Hz];
            float xc = gb[r][j + 2 * Hz];
            float xo = gb[r][j + 3 * Hz];
            float ii = 1.f / (1.f + expf(-xi));
            float ff = 1.f / (1.f + expf(-xf));
            float gg = tanhf(xc);
            float oo = 1.f / (1.f + expf(-xo));
            float c  = ff * cs[r][j] + ii * gg;
            float h  = oo * tanhf(c);
            cs[r][j] = c;
            hs[r][j] = h;
            size_t o = ((size_t)(b0 + r) * Lz + pos) * Dz + dir * Hz + j;
            __nv_bfloat16 bh, bl;
            split2(h, bh, bl);
            g_Hh[o] = bh; g_Hl[o] = bl;
        }
        __syncthreads();

        if (t + 1 < Lz) {
            #pragma unroll
            for (int r = 0; r < 8; r++) xcur[r] = xnext[r];
        }
    }
}

// ---------------- tag projection (writes TRANSPOSED logits [L][B][T]) ----------------
__global__ __launch_bounds__(256) void logits_kernel(
    const float* __restrict__ H2, const float* __restrict__ Wt, const float* __restrict__ bt)
{
    __shared__ float wts[Tz * Dz];
    __shared__ float bts[Tz];
    for (int i = threadIdx.x; i < Tz * Dz; i += 256) wts[i] = Wt[i];
    if (threadIdx.x < Tz) bts[threadIdx.x] = bt[threadIdx.x];
    __syncthreads();

    int n    = (blockIdx.x * 256 + threadIdx.x) >> 5;
    int lane = threadIdx.x & 31;
    if (n >= NL) return;
    float acc[Tz];
    #pragma unroll
    for (int t = 0; t < Tz; t++) acc[t] = 0.f;
    const float* hrow = H2 + (size_t)n * Dz;
    for (int k = lane; k < Dz; k += 32) {
        float x = hrow[k];
        #pragma unroll
        for (int t = 0; t < Tz; t++) acc[t] = fmaf(x, wts[t * Dz + k], acc[t]);
    }
    #pragma unroll
    for (int t = 0; t < Tz; t++)
        #pragma unroll
        for (int off = 16; off; off >>= 1)
            acc[t] += __shfl_xor_sync(0xffffffffu, acc[t], off);
    if (lane == 0) {
        int b = n / Lz, l = n % Lz;
        size_t o = ((size_t)l * Bz + b) * Tz;
        #pragma unroll
        for (int t = 0; t < Tz; t++) {
            float x = acc[t] + bts[t];
            g_logits[o + t] = (x >= 0.f ? x : 0.01f * x);
        }
    }
}

// ---------------- per-sample Viterbi (smem backpointers, packed 3b x 6) ----------------
#define VIT_SMEM (Lz * 128 * 4)
__global__ __launch_bounds__(128) void viterbi_kernel(const float* __restrict__ trans,
                                                      float* __restrict__ out,
                                                      int score_off, int path_off)
{
    extern __shared__ uint32_t bps[];    // [Lz][128]
    __shared__ float tr[Tz * Tz];
    int tid = threadIdx.x;
    if (tid < Tz * Tz) tr[tid] = trans[tid];
    __syncthreads();
    int b = blockIdx.x * 128 + tid;

    float prev[Tz];
    #pragma unroll
    for (int t = 0; t < Tz; t++) prev[t] = g_logits[(size_t)b * Tz + t];

    for (int l = 1; l < Lz; l++) {
        float ob[Tz];
        const float* lg = g_logits + ((size_t)l * Bz + b) * Tz;
        #pragma unroll
        for (int t = 0; t < Tz; t++) ob[t] = lg[t];
        float cur[Tz];
        uint32_t packed = 0;
        #pragma unroll
        for (int j = 0; j < Tz; j++) {
            float best = prev[0] + tr[j];
            int bi = 0;
            #pragma unroll
            for (int i = 1; i < Tz; i++) {
                float v = prev[i] + tr[i * Tz + j];
                if (v > best) { best = v; bi = i; }
            }
            packed |= (uint32_t)bi << (3 * j);
            cur[j] = ob[j] + best;
        }
        bps[l * 128 + tid] = packed;
        #pragma unroll
        for (int j = 0; j < Tz; j++) prev[j] = cur[j];
    }
    float best = prev[0];
    int last = 0;
    #pragma unroll
    for (int i = 1; i < Tz; i++) if (prev[i] > best) { best = prev[i]; last = i; }

    if (score_off >= 0) out[score_off + b] = best;
    if (path_off >= 0) {
        int tag = last;
        out[path_off + (size_t)b * Lz + (Lz - 1)] = (float)tag;
        for (int l = Lz - 1; l >= 1; l--) {
            tag = (bps[l * 128 + tid] >> (3 * tag)) & 7;
            out[path_off + (size_t)b * Lz + (l - 1)] = (float)tag;
        }
    }
}

// ---------------- launch ----------------
extern "C" void kernel_launch(void* const* d_in, const int* in_sizes, int n_in,
                              void* d_out, int out_size) {
    const int*   sent  = (const int*)d_in[0];
    const float* emb   = (const float*)d_in[2];
    const float* Wih_f = (const float*)d_in[3];
    const float* Whh_f = (const float*)d_in[4];
    const float* bih_f = (const float*)d_in[5];
    const float* bhh_f = (const float*)d_in[6];
    const float* Wih_b = (const float*)d_in[7];
    const float* Whh_b = (const float*)d_in[8];
    const float* bih_b = (const float*)d_in[9];
    const float* bhh_b = (const float*)d_in[10];
    const float* W1    = (const float*)d_in[11];
    const float* b1    = (const float*)d_in[12];
    const float* W2    = (const float*)d_in[13];
    const float* b2    = (const float*)d_in[14];
    const float* Wt    = (const float*)d_in[15];
    const float* bt    = (const float*)d_in[16];
    const float* trans = (const float*)d_in[17];
    float* out = (float*)d_out;

    float *X, *xgf, *xgb;
    __nv_bfloat16 *Xh, *Xl, *Hh, *Hl, *M1h, *M1l;
    __nv_bfloat16 *WFh, *WFl, *WBh, *WBl, *W1h, *W1l, *W2h, *W2l;
    cudaGetSymbolAddress((void**)&X,   g_X);
    cudaGetSymbolAddress((void**)&xgf, g_xgf);
    cudaGetSymbolAddress((void**)&xgb, g_xgb);
    cudaGetSymbolAddress((void**)&Xh, g_Xh);   cudaGetSymbolAddress((void**)&Xl, g_Xl);
    cudaGetSymbolAddress((void**)&Hh, g_Hh);   cudaGetSymbolAddress((void**)&Hl, g_Hl);
    cudaGetSymbolAddress((void**)&M1h, g_M1h); cudaGetSymbolAddress((void**)&M1l, g_M1l);
    cudaGetSymbolAddress((void**)&WFh, g_WFh); cudaGetSymbolAddress((void**)&WFl, g_WFl);
    cudaGetSymbolAddress((void**)&WBh, g_WBh); cudaGetSymbolAddress((void**)&WBl, g_WBl);
    cudaGetSymbolAddress((void**)&W1h, g_W1h); cudaGetSymbolAddress((void**)&W1l, g_W1l);
    cudaGetSymbolAddress((void**)&W2h, g_W2h); cudaGetSymbolAddress((void**)&W2l, g_W2l);

    cudaFuncSetAttribute(gemm_mma, cudaFuncAttributeMaxDynamicSharedMemorySize, GEMM_SMEM);
    cudaFuncSetAttribute(viterbi_kernel, cudaFuncAttributeMaxDynamicSharedMemorySize, VIT_SMEM);
    cudaFuncSetAttribute(lstm_kernel, cudaFuncAttributeMaxDynamicSharedMemorySize, LSTM_DYN);

    // zero only needed if output has a tail we never write
    if (out_size > Bz * (Lz + 1))
        cudaMemsetAsync(d_out, 0, (size_t)out_size * sizeof(float));

    // 1. gather + convert embeddings
    gather_conv<<<NL * (Ez / 4) / 256, 256>>>(sent, emb);
    // 2. convert all GEMM weights (single launch) + repack Whh
    conv_all<<<1536, 256>>>(Wih_f, Wih_b, W1, W2);
    prep_whh<<<(G4 * Hz + 255) / 256, 256>>>(Whh_f, Whh_b);
    // 3. input-gate GEMMs (HMMA split-bf16, pipelined)
    gemm_mma<<<dim3(G4 / 128, NL / 128), 256, GEMM_SMEM>>>(
        Xh, Xl, WFh, WFl, bih_f, bhh_f, xgf, nullptr, nullptr, G4, 0);
    gemm_mma<<<dim3(G4 / 128, NL / 128), 256, GEMM_SMEM>>>(
        Xh, Xl, WBh, WBl, bih_b, bhh_b, xgb, nullptr, nullptr, G4, 0);
    // 4. BiLSTM recurrence (6th launch -> ncu capture)
    lstm_kernel<<<dim3(Bz / 8, 2), 512, LSTM_DYN>>>();
    // 5. MLP1 (split2 out) and MLP2 (fp32 out)
    gemm_mma<<<dim3(Dz / 128, NL / 128), 256, GEMM_SMEM>>>(
        Hh, Hl, W1h, W1l, b1, nullptr, nullptr, M1h, M1l, Dz, 2);
    gemm_mma<<<dim3(Dz / 128, NL / 128), 256, GEMM_SMEM>>>(
        M1h, M1l, W2h, W2l, b2, nullptr, X, nullptr, nullptr, Dz, 1);
    // 6. tag projection (transposed logits)
    logits_kernel<<<NL / 8, 256>>>(X, Wt, bt);
    // 7. viterbi + output
    int score_off = -1, path_off = -1;
    if (out_size >= Bz * (Lz + 1))      { score_off = 0; path_off = Bz; }
    else if (out_size >= Bz * Lz)       { path_off = 0; }
    else                                { score_off = 0; }
    viterbi_kernel<<<Bz / 128, 128, VIT_SMEM>>>(trans, out, score_off, path_off);
}

// round 14
// speedup vs baseline: 1.1297x; 1.1297x over previous
#include <cuda_runtime.h>
#include <cuda_bf16.h>
#include <cstdint>
#include <math.h>

#define Bz 512
#define Lz 200
#define Ez 256
#define Hz 128
#define G4 512          // 4*H
#define Dz 256
#define Tz 6
#define NL (Bz*Lz)      // 102400

typedef unsigned long long u64t;

// ---------------- device scratch ----------------
__device__ float g_X[NL*Dz];          // h2 (MLP2 fp32 output)
__device__ float g_xgf[NL*G4];        // forward input gates (fp32)
__device__ float g_xgb[NL*G4];        // backward input gates (fp32)
__device__ float g_logits[NL*Tz];     // emissions, TRANSPOSED layout [L][B][T]
__device__ float g_Whh4_f[Hz*G4];
__device__ float g_Whh4_b[Hz*G4];

// bf16 split-2 operand buffers (value = hi + lo)
__device__ __nv_bfloat16 g_Xh[NL*Ez],  g_Xl[NL*Ez];     // embeddings
__device__ __nv_bfloat16 g_Hh[NL*Dz],  g_Hl[NL*Dz];     // BiLSTM hidden
__device__ __nv_bfloat16 g_M1h[NL*Dz], g_M1l[NL*Dz];    // MLP1 out
__device__ __nv_bfloat16 g_WFh[G4*Ez], g_WFl[G4*Ez];    // Wih_f
__device__ __nv_bfloat16 g_WBh[G4*Ez], g_WBl[G4*Ez];    // Wih_b
__device__ __nv_bfloat16 g_W1h[Dz*Dz], g_W1l[Dz*Dz];
__device__ __nv_bfloat16 g_W2h[Dz*Dz], g_W2l[Dz*Dz];

// ================= helpers =================
__device__ __forceinline__ uint32_t smem_u32(const void* p) {
    uint32_t a;
    asm("{ .reg .u64 t; cvta.to.shared.u64 t, %1; cvt.u32.u64 %0, t; }" : "=r"(a) : "l"(p));
    return a;
}
__device__ __forceinline__ uint32_t swz(uint32_t off) {        // SW128-style XOR swizzle
    return off ^ ((off >> 3) & 0x70);
}
__device__ __forceinline__ void ldm4(uint32_t* r, uint32_t addr) {
    asm volatile("ldmatrix.sync.aligned.m8n8.x4.shared.b16 {%0,%1,%2,%3}, [%4];"
        : "=r"(r[0]), "=r"(r[1]), "=r"(r[2]), "=r"(r[3]) : "r"(addr));
}
__device__ __forceinline__ void mma16816(float* d, const uint32_t* a, const uint32_t* b) {
    asm volatile("mma.sync.aligned.m16n8k16.row.col.f32.bf16.bf16.f32 "
        "{%0,%1,%2,%3}, {%4,%5,%6,%7}, {%8,%9}, {%0,%1,%2,%3};"
        : "+f"(d[0]), "+f"(d[1]), "+f"(d[2]), "+f"(d[3])
        : "r"(a[0]), "r"(a[1]), "r"(a[2]), "r"(a[3]), "r"(b[0]), "r"(b[1]));
}
__device__ __forceinline__ void split2(float x, __nv_bfloat16& h, __nv_bfloat16& l) {
    h = __float2bfloat16(x);
    l = __float2bfloat16(x - __bfloat162float(h));
}
__device__ __forceinline__ void cp16(uint32_t dst, const void* src) {
    asm volatile("cp.async.cg.shared.global [%0], [%1], 16;" :: "r"(dst), "l"(src));
}
// packed f32x2 FMA (Blackwell). Pure (no memory side effects) -> schedulable.
__device__ __forceinline__ u64t fma2(u64t a, u64t b, u64t c) {
    u64t d;
    asm("fma.rn.f32x2 %0, %1, %2, %3;" : "=l"(d) : "l"(a), "l"(b), "l"(c));
    return d;
}
__device__ __forceinline__ u64t pack2(float x, float y) {
    u64t r; asm("mov.b64 %0, {%1, %2};" : "=l"(r) : "f"(x), "f"(y)); return r;
}
__device__ __forceinline__ float hadd2(u64t v) {
    float x, y;
    asm("mov.b64 {%0, %1}, %2;" : "=f"(x), "=f"(y) : "l"(v));
    return x + y;
}

// ---------------- gather embeddings -> bf16 split2 ----------------
__global__ void gather_conv(const int* __restrict__ sent, const float* __restrict__ emb) {
    int idx = blockIdx.x * 256 + threadIdx.x;     // float4 units over NL x 256
    if (idx >= NL * (Ez / 4)) return;
    int n = idx >> 6, e4 = idx & 63;
    int tok = sent[n];
    float4 v = ((const float4*)emb)[(size_t)tok * 64 + e4];
    size_t o = (size_t)idx * 4;
    float vv[4] = {v.x, v.y, v.z, v.w};
    __nv_bfloat16 hh[4], ll[4];
    #pragma unroll
    for (int k = 0; k < 4; k++) split2(vv[k], hh[k], ll[k]);
    __nv_bfloat162 p;
    p.x = hh[0]; p.y = hh[1]; ((__nv_bfloat162*)(g_Xh + o))[0] = p;
    p.x = hh[2]; p.y = hh[3]; ((__nv_bfloat162*)(g_Xh + o))[1] = p;
    p.x = ll[0]; p.y = ll[1]; ((__nv_bfloat162*)(g_Xl + o))[0] = p;
    p.x = ll[2]; p.y = ll[3]; ((__nv_bfloat162*)(g_Xl + o))[1] = p;
}

// ---------------- all weight prep in ONE kernel ----------------
// conv: WF (131072), WB (131072), W1 (65536), W2 (65536)  [0, 393216)
// prep_whh: 65536 elements                                 [393216, 458752)
__global__ void conv_all(const float* __restrict__ Wih_f, const float* __restrict__ Wih_b,
                         const float* __restrict__ W1, const float* __restrict__ W2,
                         const float* __restrict__ Whh_f, const float* __restrict__ Whh_b) {
    int i = blockIdx.x * 256 + threadIdx.x;
    if (i < 393216) {
        const float* src; __nv_bfloat16 *hi, *lo; int off;
        if (i < 131072)      { src = Wih_f; hi = g_WFh; lo = g_WFl; off = i; }
        else if (i < 262144) { src = Wih_b; hi = g_WBh; lo = g_WBl; off = i - 131072; }
        else if (i < 327680) { src = W1;    hi = g_W1h; lo = g_W1l; off = i - 262144; }
        else                 { src = W2;    hi = g_W2h; lo = g_W2l; off = i - 327680; }
        __nv_bfloat16 h, l;
        split2(src[off], h, l);
        hi[off] = h; lo[off] = l;
    } else if (i < 458752) {
        int idx = i - 393216;
        int g = idx / Hz, k = idx % Hz;
        int dst = (k >> 2) * (G4 * 4) + g * 4 + (k & 3);
        g_Whh4_f[dst] = Whh_f[idx];
        g_Whh4_b[dst] = Whh_b[idx];
    }
}

// ================= HMMA split-bf16 GEMM (cp.async double-buffered) =================
#define GEMM_SMEM 65536
__global__ __launch_bounds__(256, 2) void gemm_mma(
    const __nv_bfloat16* __restrict__ Ah, const __nv_bfloat16* __restrict__ Al,
    const __nv_bfloat16* __restrict__ Bh, const __nv_bfloat16* __restrict__ Bl,
    const float* __restrict__ bias1, const float* __restrict__ bias2,
    float* __restrict__ Cf,
    __nv_bfloat16* __restrict__ C2h, __nv_bfloat16* __restrict__ C2l,
    int Mout, int mode)
{
    extern __shared__ __align__(1024) char dynsm[];
    uint32_t smem_base = smem_u32(dynsm);

    int tid = threadIdx.x, wid = tid >> 5, lane = tid & 31;
    int row0 = blockIdx.y * 128;
    int col0 = blockIdx.x * 128;
    int wm0 = (wid & 1) * 64;
    int wn0 = (wid >> 1) * 32;

    float acc[4][4][4];
    #pragma unroll
    for (int i = 0; i < 4; i++)
        #pragma unroll
        for (int j = 0; j < 4; j++)
            #pragma unroll
            for (int k = 0; k < 4; k++) acc[i][j][k] = 0.f;

    int arow = ((lane >> 3) & 1) * 8 + (lane & 7);
    int acb  = (lane >> 4) << 4;
    int brow = ((lane >> 4) << 3) + (lane & 7);
    int bcb  = ((lane >> 3) & 1) << 4;

#define LOAD_CHUNK(kcv, bufi) do {                                                      \
        int k0_ = (kcv) * 32;                                                           \
        uint32_t sb_ = smem_base + (bufi) * 32768;                                      \
        _Pragma("unroll")                                                               \
        for (int j_ = 0; j_ < 4; j_++) {                                                \
            int idx_ = tid + j_ * 256;                                                  \
            int r_ = idx_ >> 3, s_ = idx_ & 7;                                          \
            const __nv_bfloat16* pa_ = (s_ < 4 ? Ah : Al) + (size_t)(row0 + r_) * 256 + k0_ + (s_ & 3) * 8; \
            cp16(sb_ + swz(r_ * 128 + s_ * 16), pa_);                                   \
            const __nv_bfloat16* pb_ = (s_ < 4 ? Bh : Bl) + (size_t)(col0 + r_) * 256 + k0_ + (s_ & 3) * 8; \
            cp16(sb_ + 16384 + swz(r_ * 128 + s_ * 16), pb_);                           \
        }                                                                               \
        asm volatile("cp.async.commit_group;" ::: "memory");                            \
    } while (0)

    LOAD_CHUNK(0, 0);

    for (int kc = 0; kc < 8; kc++) {
        if (kc < 7) {
            LOAD_CHUNK(kc + 1, (kc + 1) & 1);
            asm volatile("cp.async.wait_group 1;" ::: "memory");
        } else {
            asm volatile("cp.async.wait_group 0;" ::: "memory");
        }
        __syncthreads();

        uint32_t sA = smem_base + (kc & 1) * 32768;
        uint32_t sB = sA + 16384;

        #pragma unroll
        for (int ks = 0; ks < 2; ks++) {
            uint32_t aH[4][4], aL[4][4], bH[2][4], bL[2][4];
            #pragma unroll
            for (int am = 0; am < 4; am++) {
                int r = wm0 + am * 16 + arow;
                ldm4(aH[am], sA + swz((uint32_t)(r * 128 + ks * 32 + acb)));
                ldm4(aL[am], sA + swz((uint32_t)(r * 128 + 64 + ks * 32 + acb)));
            }
            #pragma unroll
            for (int np = 0; np < 2; np++) {
                int r = wn0 + np * 16 + brow;
                ldm4(bH[np], sB + swz((uint32_t)(r * 128 + ks * 32 + bcb)));
                ldm4(bL[np], sB + swz((uint32_t)(r * 128 + 64 + ks * 32 + bcb)));
            }
            #pragma unroll
            for (int am = 0; am < 4; am++) {
                #pragma unroll
                for (int bn = 0; bn < 4; bn++) {
                    const uint32_t* bh = &bH[bn >> 1][(bn & 1) * 2];
                    const uint32_t* bl = &bL[bn >> 1][(bn & 1) * 2];
                    mma16816(acc[am][bn], aH[am], bh);
                    mma16816(acc[am][bn], aH[am], bl);
                    mma16816(acc[am][bn], aL[am], bh);
                }
            }
        }
        __syncthreads();
    }
#undef LOAD_CHUNK

    int rg = row0 + wm0 + (lane >> 2);
    int cg = col0 + wn0 + (lane & 3) * 2;
    #pragma unroll
    for (int bn = 0; bn < 4; bn++) {
        int col = cg + bn * 8;
        float bb0 = bias1[col]     + (bias2 ? bias2[col]     : 0.f);
        float bb1 = bias1[col + 1] + (bias2 ? bias2[col + 1] : 0.f);
        #pragma unroll
        for (int am = 0; am < 4; am++) {
            #pragma unroll
            for (int half = 0; half < 2; half++) {
                int row = rg + am * 16 + half * 8;
                float x0 = acc[am][bn][half * 2]     + bb0;
                float x1 = acc[am][bn][half * 2 + 1] + bb1;
                if (mode) {
                    x0 = x0 >= 0.f ? x0 : 0.01f * x0;
                    x1 = x1 >= 0.f ? x1 : 0.01f * x1;
                }
                size_t base = (size_t)row * Mout + col;
                if (mode <= 1) {
                    float2 v; v.x = x0; v.y = x1;
                    *(float2*)(Cf + base) = v;
                } else {
                    __nv_bfloat16 h0, l0, h1, l1;
                    split2(x0, h0, l0);
                    split2(x1, h1, l1);
                    __nv_bfloat162 ph, pl;
                    ph.x = h0; ph.y = h1;
                    pl.x = l0; pl.y = l1;
                    *(__nv_bfloat162*)(C2h + base) = ph;
                    *(__nv_bfloat162*)(C2l + base) = pl;
                }
            }
        }
    }
}

// ---------------- BiLSTM recurrence ----------------
// Thread t -> gate pair (p, p+256), p = t&255, rows (t>>8)*4 .. +3.
// Halves the h-broadcast LDS count (128 vs 256 per thread/step).
// 24/32 kc-chunks (192KB) of Whh in dynamic SMEM; remaining 8 streamed via LDG
// each step. Accumulation order per (row,gate) unchanged (kc ascending) ->
// bitwise-identical results. EXACT activations.
#define KC_SM 24
#define KC_LD (Hz/4 - KC_SM)     // 8
#define LSTM_DYN (KC_SM * 2048 * 4)   // 196608
__global__ __launch_bounds__(512) void lstm_kernel() {
    extern __shared__ __align__(16) float sw[];    // [KC_SM][2048]
    __shared__ float hs[8][Hz];
    __shared__ float cs[8][Hz];
    __shared__ float gb[8][G4];

    int dir = blockIdx.y;
    int b0  = blockIdx.x * 8;
    const float* xg = dir ? g_xgb : g_xgf;
    const float* W4 = dir ? g_Whh4_b : g_Whh4_f;

    int t = threadIdx.x;
    int p  = t & 255;          // gate pair base: gates p and p+256
    int r0 = (t >> 8) * 4;     // rows r0..r0+3

    // cooperative smem weight load
    for (int i = t * 4; i < KC_SM * 2048; i += 512 * 4)
        *(float4*)(sw + i) = *(const float4*)(W4 + i);
    for (int idx = t; idx < 8 * Hz; idx += 512) {
        ((float*)hs)[idx] = 0.f;
        ((float*)cs)[idx] = 0.f;
    }
    __syncthreads();

    const float* wgs = W4 + KC_SM * 2048;   // streamed chunks base

    int pos0 = dir ? (Lz - 1) : 0;
    int sdir = dir ? -1 : 1;

    // preload xg for step 0: [rr][gg]
    float xcur[4][2];
    #pragma unroll
    for (int rr = 0; rr < 4; rr++) {
        size_t rowb = ((size_t)(b0 + r0 + rr) * Lz + pos0) * G4;
        xcur[rr][0] = xg[rowb + p];
        xcur[rr][1] = xg[rowb + p + 256];
    }

    for (int tt = 0; tt < Lz; tt++) {
        int pos = pos0 + tt * sdir;

        // stream the 8 non-smem weight chunks for both gates (hidden behind matvec)
        ulonglong2 wl0[KC_LD], wl1[KC_LD];
        #pragma unroll
        for (int kc = 0; kc < KC_LD; kc++) {
            wl0[kc] = *(const ulonglong2*)(wgs + kc * 2048 + 4 * p);
            wl1[kc] = *(const ulonglong2*)(wgs + kc * 2048 + 1024 + 4 * p);
        }

        // prefetch next step's xg
        float xnext[4][2];
        if (tt + 1 < Lz) {
            int pn = pos + sdir;
            #pragma unroll
            for (int rr = 0; rr < 4; rr++) {
                size_t rowb = ((size_t)(b0 + r0 + rr) * Lz + pn) * G4;
                xnext[rr][0] = xg[rowb + p];
                xnext[rr][1] = xg[rowb + p + 256];
            }
        }

        u64t acc[4][2];
        #pragma unroll
        for (int rr = 0; rr < 4; rr++) {
            acc[rr][0] = pack2(xcur[rr][0], 0.f);
            acc[rr][1] = pack2(xcur[rr][1], 0.f);
        }

        // smem-weight portion (kc 0..KC_SM-1)
        #pragma unroll 4
        for (int kc = 0; kc < KC_SM; kc++) {
            ulonglong2 w0 = *(const ulonglong2*)(sw + kc * 2048 + 4 * p);
            ulonglong2 w1 = *(const ulonglong2*)(sw + kc * 2048 + 1024 + 4 * p);
            #pragma unroll
            for (int rr = 0; rr < 4; rr++) {
                ulonglong2 hv = *(const ulonglong2*)(&hs[r0 + rr][kc << 2]);
                acc[rr][0] = fma2(w0.x, hv.x, acc[rr][0]);
                acc[rr][0] = fma2(w0.y, hv.y, acc[rr][0]);
                acc[rr][1] = fma2(w1.x, hv.x, acc[rr][1]);
                acc[rr][1] = fma2(w1.y, hv.y, acc[rr][1]);
            }
        }
        // streamed weight portion (kc KC_SM..31)
        #pragma unroll
        for (int kc = 0; kc < KC_LD; kc++) {
            #pragma unroll
            for (int rr = 0; rr < 4; rr++) {
                ulonglong2 hv = *(const ulonglong2*)(&hs[r0 + rr][(KC_SM + kc) << 2]);
                acc[rr][0] = fma2(wl0[kc].x, hv.x, acc[rr][0]);
                acc[rr][0] = fma2(wl0[kc].y, hv.y, acc[rr][0]);
                acc[rr][1] = fma2(wl1[kc].x, hv.x, acc[rr][1]);
                acc[rr][1] = fma2(wl1[kc].y, hv.y, acc[rr][1]);
            }
        }
        #pragma unroll
        for (int rr = 0; rr < 4; rr++) {
            gb[r0 + rr][p]       = hadd2(acc[rr][0]);
            gb[r0 + rr][p + 256] = hadd2(acc[rr][1]);
        }
        __syncthreads();

        #pragma unroll
        for (int rep = 0; rep < 2; rep++) {
            int idx = rep * 512 + t;
            int r = idx >> 7, j = idx & 127;
            float xi = gb[r][j];
            float xf = gb[r][j + Hz];
            float xc = gb[r][j + 2 * Hz];
            float xo = gb[r][j + 3 * Hz];
            float ii = 1.f / (1.f + expf(-xi));
            float ff = 1.f / (1.f + expf(-xf));
            float gg = tanhf(xc);
            float oo = 1.f / (1.f + expf(-xo));
            float c  = ff * cs[r][j] + ii * gg;
            float h  = oo * tanhf(c);
            cs[r][j] = c;
            hs[r][j] = h;
            size_t o = ((size_t)(b0 + r) * Lz + pos) * Dz + dir * Hz + j;
            __nv_bfloat16 bh, bl;
            split2(h, bh, bl);
            g_Hh[o] = bh; g_Hl[o] = bl;
        }
        __syncthreads();

        if (tt + 1 < Lz) {
            #pragma unroll
            for (int rr = 0; rr < 4; rr++) {
                xcur[rr][0] = xnext[rr][0];
                xcur[rr][1] = xnext[rr][1];
            }
        }
    }
}

// ---------------- tag projection (writes TRANSPOSED logits [L][B][T]) ----------------
__global__ __launch_bounds__(256) void logits_kernel(
    const float* __restrict__ H2, const float* __restrict__ Wt, const float* __restrict__ bt)
{
    __shared__ float wts[Tz * Dz];
    __shared__ float bts[Tz];
    for (int i = threadIdx.x; i < Tz * Dz; i += 256) wts[i] = Wt[i];
    if (threadIdx.x < Tz) bts[threadIdx.x] = bt[threadIdx.x];
    __syncthreads();

    int n    = (blockIdx.x * 256 + threadIdx.x) >> 5;
    int lane = threadIdx.x & 31;
    if (n >= NL) return;
    float acc[Tz];
    #pragma unroll
    for (int t = 0; t < Tz; t++) acc[t] = 0.f;
    const float* hrow = H2 + (size_t)n * Dz;
    for (int k = lane; k < Dz; k += 32) {
        float x = hrow[k];
        #pragma unroll
        for (int t = 0; t < Tz; t++) acc[t] = fmaf(x, wts[t * Dz + k], acc[t]);
    }
    #pragma unroll
    for (int t = 0; t < Tz; t++)
        #pragma unroll
        for (int off = 16; off; off >>= 1)
            acc[t] += __shfl_xor_sync(0xffffffffu, acc[t], off);
    if (lane == 0) {
        int b = n / Lz, l = n % Lz;
        size_t o = ((size_t)l * Bz + b) * Tz;
        #pragma unroll
        for (int t = 0; t < Tz; t++) {
            float x = acc[t] + bts[t];
            g_logits[o + t] = (x >= 0.f ? x : 0.01f * x);
        }
    }
}

// ---------------- per-sample Viterbi (smem backpointers, packed 3b x 6) ----------------
#define VIT_SMEM (Lz * 128 * 4)
__global__ __launch_bounds__(128) void viterbi_kernel(const float* __restrict__ trans,
                                                      float* __restrict__ out,
                                                      int score_off, int path_off)
{
    extern __shared__ uint32_t bps[];    // [Lz][128]
    __shared__ float tr[Tz * Tz];
    int tid = threadIdx.x;
    if (tid < Tz * Tz) tr[tid] = trans[tid];
    __syncthreads();
    int b = blockIdx.x * 128 + tid;

    float prev[Tz];
    #pragma unroll
    for (int t = 0; t < Tz; t++) prev[t] = g_logits[(size_t)b * Tz + t];

    for (int l = 1; l < Lz; l++) {
        float ob[Tz];
        const float* lg = g_logits + ((size_t)l * Bz + b) * Tz;
        #pragma unroll
        for (int t = 0; t < Tz; t++) ob[t] = lg[t];
        float cur[Tz];
        uint32_t packed = 0;
        #pragma unroll
        for (int j = 0; j < Tz; j++) {
            float best = prev[0] + tr[j];
            int bi = 0;
            #pragma unroll
            for (int i = 1; i < Tz; i++) {
                float v = prev[i] + tr[i * Tz + j];
                if (v > best) { best = v; bi = i; }
            }
            packed |= (uint32_t)bi << (3 * j);
            cur[j] = ob[j] + best;
        }
        bps[l * 128 + tid] = packed;
        #pragma unroll
        for (int j = 0; j < Tz; j++) prev[j] = cur[j];
    }
    float best = prev[0];
    int last = 0;
    #pragma unroll
    for (int i = 1; i < Tz; i++) if (prev[i] > best) { best = prev[i]; last = i; }

    if (score_off >= 0) out[score_off + b] = best;
    if (path_off >= 0) {
        int tag = last;
        out[path_off + (size_t)b * Lz + (Lz - 1)] = (float)tag;
        for (int l = Lz - 1; l >= 1; l--) {
            tag = (bps[l * 128 + tid] >> (3 * tag)) & 7;
            out[path_off + (size_t)b * Lz + (l - 1)] = (float)tag;
        }
    }
}

// ---------------- launch ----------------
extern "C" void kernel_launch(void* const* d_in, const int* in_sizes, int n_in,
                              void* d_out, int out_size) {
    const int*   sent  = (const int*)d_in[0];
    const float* emb   = (const float*)d_in[2];
    const float* Wih_f = (const float*)d_in[3];
    const float* Whh_f = (const float*)d_in[4];
    const float* bih_f = (const float*)d_in[5];
    const float* bhh_f = (const float*)d_in[6];
    const float* Wih_b = (const float*)d_in[7];
    const float* Whh_b = (const float*)d_in[8];
    const float* bih_b = (const float*)d_in[9];
    const float* bhh_b = (const float*)d_in[10];
    const float* W1    = (const float*)d_in[11];
    const float* b1    = (const float*)d_in[12];
    const float* W2    = (const float*)d_in[13];
    const float* b2    = (const float*)d_in[14];
    const float* Wt    = (const float*)d_in[15];
    const float* bt    = (const float*)d_in[16];
    const float* trans = (const float*)d_in[17];
    float* out = (float*)d_out;

    float *X, *xgf, *xgb;
    __nv_bfloat16 *Xh, *Xl, *Hh, *Hl, *M1h, *M1l;
    __nv_bfloat16 *WFh, *WFl, *WBh, *WBl, *W1h, *W1l, *W2h, *W2l;
    cudaGetSymbolAddress((void**)&X,   g_X);
    cudaGetSymbolAddress((void**)&xgf, g_xgf);
    cudaGetSymbolAddress((void**)&xgb, g_xgb);
    cudaGetSymbolAddress((void**)&Xh, g_Xh);   cudaGetSymbolAddress((void**)&Xl, g_Xl);
    cudaGetSymbolAddress((void**)&Hh, g_Hh);   cudaGetSymbolAddress((void**)&Hl, g_Hl);
    cudaGetSymbolAddress((void**)&M1h, g_M1h); cudaGetSymbolAddress((void**)&M1l, g_M1l);
    cudaGetSymbolAddress((void**)&WFh, g_WFh); cudaGetSymbolAddress((void**)&WFl, g_WFl);
    cudaGetSymbolAddress((void**)&WBh, g_WBh); cudaGetSymbolAddress((void**)&WBl, g_WBl);
    cudaGetSymbolAddress((void**)&W1h, g_W1h); cudaGetSymbolAddress((void**)&W1l, g_W1l);
    cudaGetSymbolAddress((void**)&W2h, g_W2h); cudaGetSymbolAddress((void**)&W2l, g_W2l);

    cudaFuncSetAttribute(gemm_mma, cudaFuncAttributeMaxDynamicSharedMemorySize, GEMM_SMEM);
    cudaFuncSetAttribute(viterbi_kernel, cudaFuncAttributeMaxDynamicSharedMemorySize, VIT_SMEM);
    cudaFuncSetAttribute(lstm_kernel, cudaFuncAttributeMaxDynamicSharedMemorySize, LSTM_DYN);

    // zero only needed if output has a tail we never write
    if (out_size > Bz * (Lz + 1))
        cudaMemsetAsync(d_out, 0, (size_t)out_size * sizeof(float));

    // launch 1: gather + convert embeddings
    gather_conv<<<NL * (Ez / 4) / 256, 256>>>(sent, emb);
    // launch 2: ALL weight conversions + Whh repack (single kernel)
    conv_all<<<1792, 256>>>(Wih_f, Wih_b, W1, W2, Whh_f, Whh_b);
    // launches 3,4: input-gate GEMMs
    gemm_mma<<<dim3(G4 / 128, NL / 128), 256, GEMM_SMEM>>>(
        Xh, Xl, WFh, WFl, bih_f, bhh_f, xgf, nullptr, nullptr, G4, 0);
    gemm_mma<<<dim3(G4 / 128, NL / 128), 256, GEMM_SMEM>>>(
        Xh, Xl, WBh, WBl, bih_b, bhh_b, xgb, nullptr, nullptr, G4, 0);
    // launch 5: BiLSTM recurrence  <-- ncu -s 5 capture slot
    lstm_kernel<<<dim3(Bz / 8, 2), 512, LSTM_DYN>>>();
    // launches 6,7: MLP
    gemm_mma<<<dim3(Dz / 128, NL / 128), 256, GEMM_SMEM>>>(
        Hh, Hl, W1h, W1l, b1, nullptr, nullptr, M1h, M1l, Dz, 2);
    gemm_mma<<<dim3(Dz / 128, NL / 128), 256, GEMM_SMEM>>>(
        M1h, M1l, W2h, W2l, b2, nullptr, X, nullptr, nullptr, Dz, 1);
    // launch 8: tag projection (transposed logits)
    logits_kernel<<<NL / 8, 256>>>(X, Wt, bt);
    // launch 9: viterbi + output
    int score_off = -1, path_off = -1;
    if (out_size >= Bz * (Lz + 1))      { score_off = 0; path_off = Bz; }
    else if (out_size >= Bz * Lz)       { path_off = 0; }
    else                                { score_off = 0; }
    viterbi_kernel<<<Bz / 128, 128, VIT_SMEM>>>(trans, out, score_off, path_off);
}